// round 16
// baseline (speedup 1.0000x reference)
#include <cuda_runtime.h>
#include <cuda_bf16.h>
#include <stdint.h>

#define BATCH   256
#define NWARM   128
#define FEAT    1024
#define HID     2048
#define TSTEPS  128
#define OUT_T   (TSTEPS + 1)
#define LDOUT   (OUT_T * FEAT)

// Scratch (small statics only — large __device__ statics crash the container).
// h is NEVER materialized: consumers reduce h-partials in their prologues.
__device__ float g_part[2][2][BATCH * HID];   // [pingpong][z-half] h partials (8MB)
__device__ float g_fcpart[2][BATCH * FEAT];   // fc partials (2MB)
__device__ float g_bias_cell[HID];

// init: bias_cell; encode h0 = 0 as p0 = -bias_cell, p1 = 0
// so relu(p0 + p1 + bias_cell) == 0 exactly.
__global__ void init_kernel(const float* __restrict__ b_ih,
                            const float* __restrict__ b_hh)
{
    int i = blockIdx.x * blockDim.x + threadIdx.x;
    if (i < HID) g_bias_cell[i] = b_ih[i] + b_hh[i];
    if (i < BATCH * HID) {
        int c = i & (HID - 1);
        g_part[0][0][i] = -(b_ih[c] + b_hh[c]);
        g_part[0][1][i] = 0.0f;
    }
}

__device__ __forceinline__ uint32_t smem_u32(const void* p) {
    uint32_t a;
    asm("{ .reg .u64 t; cvta.to.shared.u64 t, %1; cvt.u32.u64 %0, t; }"
        : "=r"(a) : "l"(p));
    return a;
}

// hi = top 16 bits of fp32 (exact trunc), lo = rn_bf16(f - hi); packed pairs.
__device__ __forceinline__ void split4(float4 v, uint2& H, uint2& L) {
    unsigned bx = __float_as_uint(v.x), by = __float_as_uint(v.y);
    unsigned bz = __float_as_uint(v.z), bw = __float_as_uint(v.w);
    H.x = __byte_perm(bx, by, 0x7632);
    H.y = __byte_perm(bz, bw, 0x7632);
    float lx = v.x - __uint_as_float(bx & 0xFFFF0000u);
    float ly = v.y - __uint_as_float(by & 0xFFFF0000u);
    float lz = v.z - __uint_as_float(bz & 0xFFFF0000u);
    float lw = v.w - __uint_as_float(bw & 0xFFFF0000u);
    __nv_bfloat162 l0 = __floats2bfloat162_rn(lx, ly);
    __nv_bfloat162 l1 = __floats2bfloat162_rn(lz, lw);
    L.x = *(unsigned*)&l0;
    L.y = *(unsigned*)&l1;
}

__device__ __forceinline__ void mma16816(float d[4], const unsigned a[4], const unsigned b[2]) {
    asm volatile(
        "mma.sync.aligned.m16n8k16.row.col.f32.bf16.bf16.f32 "
        "{%0,%1,%2,%3}, {%4,%5,%6,%7}, {%8,%9}, {%0,%1,%2,%3};"
        : "+f"(d[0]), "+f"(d[1]), "+f"(d[2]), "+f"(d[3])
        : "r"(a[0]), "r"(a[1]), "r"(a[2]), "r"(a[3]), "r"(b[0]), "r"(b[1]));
}

__device__ __forceinline__ void ldsm4(unsigned r[4], unsigned addr) {
    asm volatile(
        "ldmatrix.sync.aligned.m8n8.x4.shared.b16 {%0,%1,%2,%3}, [%4];"
        : "=r"(r[0]), "=r"(r[1]), "=r"(r[2]), "=r"(r[3]) : "r"(addr));
}

// K-split partial GEMM. K = [plain A1 segment (K1)] ++ [fused-h segment (K2)].
// For the fused segment, A rows are computed on the fly in the PROLOGUE:
//   a = relu(HP0 + HP1 + hbias)   (redundant across CTAs, deterministic)
// Producer: LDG fp32 -> register split -> STS bf16 hi/lo; double-buffered
// planes, ONE __syncthreads per tile. D = Ah*Wh + Ah*Wl + Al*Wh.
// Writes P[z] partials only (no epilogue fusion — R15 lesson: tails kill).
// BM=64, BK=32; 256 thr, warps 2m x 2n x 2k + end smem wk-reduction.
template<int BN>
__global__ __launch_bounds__(256)
void gemm_ks(const float* __restrict__ A1, int lda1,
             const float* __restrict__ W1, int K1,
             const float* __restrict__ HP0, const float* __restrict__ HP1,
             const float* __restrict__ hbias, int lda2,
             const float* __restrict__ W2, int K2,
             float* __restrict__ P, int pstride)
{
    constexpr int PKB  = 40;                     // bf16 pitch (80B rows)
    constexpr int APB  = 64 * 80;                // A plane bytes
    constexpr int BPB  = BN * 80;                // B plane bytes
    constexpr int BUFB = 2 * APB + 2 * BPB;      // AHI|ALO|BHI|BLO
    constexpr int WNJ  = BN / 16;
    constexpr int WIW  = BN / 32;

    __shared__ __align__(16) char sm[2 * BUFB];  // 40KB (BN=64) static

    const int tid  = threadIdx.x;
    const int lane = tid & 31;
    const int wid  = tid >> 5;
    const int wk   = wid & 1;
    const int wm   = (wid >> 1) & 1;
    const int wn   = wid >> 2;
    const int bm   = blockIdx.y * 64;
    const int bn   = blockIdx.x * BN;
    const int lr   = lane >> 2;
    const int lc   = lane & 3;
    const int k0   = wk * 16;

    const int t1   = K1 >> 5;
    const int tTot = t1 + (K2 >> 5);
    const int half = tTot >> 1;
    const int tBeg = blockIdx.z * half;
    const int tEnd = tBeg + half;

    const int ldr  = tid >> 3;                   // 0..31
    const int ldc4 = (tid & 7) * 4;              // fp32 chunk in BK=32

    // ldmatrix byte offsets within a plane (R7/R13-proven formulas)
    const int offA = ((wm * 32 + ((lane >> 3) & 1) * 8 + (lane & 7)) * PKB
                      + k0 + (lane >> 4) * 8) * 2;
    const int offB = ((wn * (BN / 2) + (lane >> 4) * 8 + (lane & 7)) * PKB
                      + k0 + ((lane >> 3) & 1) * 8) * 2;
    const unsigned smBase = smem_u32(sm);

    float4 av[2];
    float4 wv[WIW];

#define LDTILE(TT)                                                           \
    do {                                                                     \
        if ((TT) < t1) {                                                     \
            int kt_ = (TT) << 5;                                             \
            _Pragma("unroll")                                                \
            for (int p = 0; p < 2; p++)                                      \
                av[p] = *(const float4*)(A1 + (size_t)(bm + ldr + p * 32) * lda1 + kt_ + ldc4); \
            _Pragma("unroll")                                                \
            for (int p = 0; p < WIW; p++)                                    \
                wv[p] = *(const float4*)(W1 + (size_t)(bn + ldr + p * 32) * K1 + kt_ + ldc4); \
        } else {                                                             \
            int kt_ = ((TT) - t1) << 5;                                      \
            float4 bb = *(const float4*)(hbias + kt_ + ldc4);                \
            _Pragma("unroll")                                                \
            for (int p = 0; p < 2; p++) {                                    \
                size_t off = (size_t)(bm + ldr + p * 32) * lda2 + kt_ + ldc4;\
                float4 x = *(const float4*)(HP0 + off);                      \
                float4 y = *(const float4*)(HP1 + off);                      \
                av[p].x = fmaxf(x.x + y.x + bb.x, 0.0f);                     \
                av[p].y = fmaxf(x.y + y.y + bb.y, 0.0f);                     \
                av[p].z = fmaxf(x.z + y.z + bb.z, 0.0f);                     \
                av[p].w = fmaxf(x.w + y.w + bb.w, 0.0f);                     \
            }                                                                \
            _Pragma("unroll")                                                \
            for (int p = 0; p < WIW; p++)                                    \
                wv[p] = *(const float4*)(W2 + (size_t)(bn + ldr + p * 32) * K2 + kt_ + ldc4); \
        }                                                                    \
    } while (0)

#define STTILE(BUF)                                                          \
    do {                                                                     \
        char* AHI_ = sm + (BUF) * BUFB;                                      \
        char* ALO_ = AHI_ + APB;                                             \
        char* BHI_ = ALO_ + APB;                                             \
        char* BLO_ = BHI_ + BPB;                                             \
        _Pragma("unroll")                                                    \
        for (int p = 0; p < 2; p++) {                                        \
            int r = ldr + p * 32;                                            \
            uint2 H, L; split4(av[p], H, L);                                 \
            *(uint2*)(AHI_ + r * 80 + ldc4 * 2) = H;                         \
            *(uint2*)(ALO_ + r * 80 + ldc4 * 2) = L;                         \
        }                                                                    \
        _Pragma("unroll")                                                    \
        for (int p = 0; p < WIW; p++) {                                      \
            int r = ldr + p * 32;                                            \
            uint2 H, L; split4(wv[p], H, L);                                 \
            *(uint2*)(BHI_ + r * 80 + ldc4 * 2) = H;                         \
            *(uint2*)(BLO_ + r * 80 + ldc4 * 2) = L;                         \
        }                                                                    \
    } while (0)

    float D[2][WNJ][4];
    #pragma unroll
    for (int i = 0; i < 2; i++)
        #pragma unroll
        for (int j = 0; j < WNJ; j++)
            #pragma unroll
            for (int q = 0; q < 4; q++) D[i][j][q] = 0.0f;

    LDTILE(tBeg);

    for (int t = tBeg; t < tEnd; t++) {
        const int buf = t & 1;
        STTILE(buf);
        __syncthreads();                         // the only sync per tile
        if (t + 1 < tEnd) LDTILE(t + 1);         // flight covers MMA phase

        const unsigned aHi = smBase + buf * BUFB + offA;
        const unsigned aLo = aHi + APB;
        const unsigned bHi = aLo + APB - offA + offB;
        const unsigned bLo = bHi + BPB;

        unsigned Ah[2][4], Al[2][4];
        #pragma unroll
        for (int mi = 0; mi < 2; mi++) {
            ldsm4(Ah[mi], aHi + mi * (16 * 80));
            ldsm4(Al[mi], aLo + mi * (16 * 80));
        }
        unsigned Bh[WNJ][2], Bl[WNJ][2];
        #pragma unroll
        for (int p = 0; p < WNJ / 2; p++) {
            unsigned t4[4];
            ldsm4(t4, bHi + p * (16 * 80));
            Bh[2*p][0] = t4[0]; Bh[2*p][1] = t4[1];
            Bh[2*p+1][0] = t4[2]; Bh[2*p+1][1] = t4[3];
            ldsm4(t4, bLo + p * (16 * 80));
            Bl[2*p][0] = t4[0]; Bl[2*p][1] = t4[1];
            Bl[2*p+1][0] = t4[2]; Bl[2*p+1][1] = t4[3];
        }
        #pragma unroll
        for (int mi = 0; mi < 2; mi++)
            #pragma unroll
            for (int nj = 0; nj < WNJ; nj++) {
                mma16816(D[mi][nj], Ah[mi], Bh[nj]);
                mma16816(D[mi][nj], Ah[mi], Bl[nj]);
                mma16816(D[mi][nj], Al[mi], Bh[nj]);
            }
    }
#undef LDTILE
#undef STTILE

    __syncthreads();                             // all ldsm done; smem reusable

    // ---- combine the two warp-level k16-partials through smem ----
    float* sRed = (float*)sm;
    const int rebase = (wm * 2 + wn) * 32 + lane;
    if (wk == 1) {
        #pragma unroll
        for (int mi = 0; mi < 2; mi++)
            #pragma unroll
            for (int nj = 0; nj < WNJ; nj++)
                #pragma unroll
                for (int q = 0; q < 4; q++)
                    sRed[((mi * WNJ + nj) * 4 + q) * 128 + rebase] = D[mi][nj][q];
    }
    __syncthreads();
    if (wk == 0) {
        float* Pk = P + (size_t)blockIdx.z * pstride;
        const int N = gridDim.x * BN;
        #pragma unroll
        for (int mi = 0; mi < 2; mi++)
            #pragma unroll
            for (int nj = 0; nj < WNJ; nj++) {
                #pragma unroll
                for (int q = 0; q < 4; q++)
                    D[mi][nj][q] += sRed[((mi * WNJ + nj) * 4 + q) * 128 + rebase];
                int r = bm + wm * 32 + mi * 16 + lr;
                int c = bn + wn * (BN / 2) + nj * 8 + lc * 2;
                *(float2*)(Pk + (size_t)r * N + c) =
                    make_float2(D[mi][nj][0], D[mi][nj][1]);
                *(float2*)(Pk + (size_t)(r + 8) * N + c) =
                    make_float2(D[mi][nj][2], D[mi][nj][3]);
            }
    }
}

// out[r, c] = p0 + p1 + bias[c] (fc output; no relu); float4-vectorized.
__global__ void reduce_kernel(const float4* __restrict__ p0,
                              const float4* __restrict__ p1,
                              const float* __restrict__ bias,
                              float* __restrict__ out,
                              int N4, int ldc, int total4)
{
    int i = blockIdx.x * blockDim.x + threadIdx.x;
    if (i >= total4) return;
    int row = i / N4, c4 = i % N4;
    float4 a = p0[i], b = p1[i];
    float4 bb = *(const float4*)&bias[c4 * 4];
    float4 v;
    v.x = a.x + b.x + bb.x;
    v.y = a.y + b.y + bb.y;
    v.z = a.z + b.z + bb.z;
    v.w = a.w + b.w + bb.w;
    *(float4*)(out + (size_t)row * ldc + c4 * 4) = v;
}

extern "C" void kernel_launch(void* const* d_in, const int* in_sizes, int n_in,
                              void* d_out, int out_size)
{
    const float* inputs = (const float*)d_in[0];   // [256,128,1024]
    const float* W_ih   = (const float*)d_in[1];   // [2048,1024]
    const float* b_ih   = (const float*)d_in[2];
    const float* W_hh   = (const float*)d_in[3];   // [2048,2048]
    const float* b_hh   = (const float*)d_in[4];
    const float* W_fc   = (const float*)d_in[5];   // [1024,2048]
    const float* b_fc   = (const float*)d_in[6];
    float* out = (float*)d_out;                    // [256,129,1024]

    float* part = nullptr; float* fcpart = nullptr; float* bias_cell = nullptr;
    cudaGetSymbolAddress((void**)&part, g_part);
    cudaGetSymbolAddress((void**)&fcpart, g_fcpart);
    cudaGetSymbolAddress((void**)&bias_cell, g_bias_cell);

    const int HSTRIDE  = BATCH * HID;     // one z-half of an h buffer
    const int FCSTRIDE = BATCH * FEAT;
    // h partial buffers: hb[b] -> z0 plane; z1 plane at +HSTRIDE
    float* hb[2] = { part, part + 2 * HSTRIDE };

    init_kernel<<<(BATCH * HID + 255) / 256, 256>>>(b_ih, b_hh);

    dim3 cellGrid(HID / 64, BATCH / 64, 2);   // 32 x 4 x 2 = 256 CTAs
    dim3 fcGrid(FEAT / 32, BATCH / 64, 2);    // 32 x 4 x 2 = 256 CTAs
    const int fcT4 = BATCH * FEAT / 4;

    int cur = 0;
    // warmup: ONE kernel per step (cell reads h-partials fused, writes partials)
    for (int t = 0; t < NWARM; t++) {
        gemm_ks<64><<<cellGrid, 256>>>(
            inputs + (size_t)t * FEAT, NWARM * FEAT, W_ih, FEAT,
            hb[cur], hb[cur] + HSTRIDE, bias_cell, HID, W_hh, HID,
            hb[cur ^ 1], HSTRIDE);
        cur ^= 1;
    }
    // pred0
    gemm_ks<32><<<fcGrid, 256>>>(
        nullptr, 0, nullptr, 0,
        hb[cur], hb[cur] + HSTRIDE, bias_cell, HID, W_fc, HID,
        fcpart, FCSTRIDE);
    reduce_kernel<<<(fcT4 + 255) / 256, 256>>>(
        (const float4*)fcpart, (const float4*)(fcpart + FCSTRIDE),
        b_fc, out, FEAT / 4, LDOUT, fcT4);
    // rollout
    for (int s = 1; s <= TSTEPS; s++) {
        gemm_ks<64><<<cellGrid, 256>>>(
            out + (size_t)(s - 1) * FEAT, LDOUT, W_ih, FEAT,
            hb[cur], hb[cur] + HSTRIDE, bias_cell, HID, W_hh, HID,
            hb[cur ^ 1], HSTRIDE);
        cur ^= 1;
        gemm_ks<32><<<fcGrid, 256>>>(
            nullptr, 0, nullptr, 0,
            hb[cur], hb[cur] + HSTRIDE, bias_cell, HID, W_fc, HID,
            fcpart, FCSTRIDE);
        reduce_kernel<<<(fcT4 + 255) / 256, 256>>>(
            (const float4*)fcpart, (const float4*)(fcpart + FCSTRIDE),
            b_fc, out + (size_t)s * FEAT, FEAT / 4, LDOUT, fcT4);
    }
}

// round 17
// speedup vs baseline: 1.2277x; 1.2277x over previous
#include <cuda_runtime.h>
#include <cuda_bf16.h>
#include <stdint.h>

#define BATCH   256
#define NWARM   128
#define FEAT    1024
#define HID     2048
#define TSTEPS  128
#define OUT_T   (TSTEPS + 1)
#define LDOUT   (OUT_T * FEAT)

// Scratch (small statics only — large __device__ statics crash the container).
__device__ float g_h[2][BATCH * HID];      // 4MB
__device__ float g_part[3][BATCH * HID];   // cell K-split partials (6MB)
__device__ float g_fcpart[2][BATCH * FEAT];// fc K-split partials (2MB)
__device__ float g_bias_cell[HID];

__global__ void init_kernel(const float* __restrict__ b_ih,
                            const float* __restrict__ b_hh)
{
    int i = blockIdx.x * blockDim.x + threadIdx.x;
    if (i < HID) g_bias_cell[i] = b_ih[i] + b_hh[i];
    if (i < BATCH * HID) g_h[0][i] = 0.0f;
}

__device__ __forceinline__ uint32_t smem_u32(const void* p) {
    uint32_t a;
    asm("{ .reg .u64 t; cvta.to.shared.u64 t, %1; cvt.u32.u64 %0, t; }"
        : "=r"(a) : "l"(p));
    return a;
}

// hi = top 16 bits of fp32 (exact trunc), lo = rn_bf16(f - hi); packed pairs.
__device__ __forceinline__ void split4(float4 v, uint2& H, uint2& L) {
    unsigned bx = __float_as_uint(v.x), by = __float_as_uint(v.y);
    unsigned bz = __float_as_uint(v.z), bw = __float_as_uint(v.w);
    H.x = __byte_perm(bx, by, 0x7632);
    H.y = __byte_perm(bz, bw, 0x7632);
    float lx = v.x - __uint_as_float(bx & 0xFFFF0000u);
    float ly = v.y - __uint_as_float(by & 0xFFFF0000u);
    float lz = v.z - __uint_as_float(bz & 0xFFFF0000u);
    float lw = v.w - __uint_as_float(bw & 0xFFFF0000u);
    __nv_bfloat162 l0 = __floats2bfloat162_rn(lx, ly);
    __nv_bfloat162 l1 = __floats2bfloat162_rn(lz, lw);
    L.x = *(unsigned*)&l0;
    L.y = *(unsigned*)&l1;
}

__device__ __forceinline__ void mma16816(float d[4], const unsigned a[4], const unsigned b[2]) {
    asm volatile(
        "mma.sync.aligned.m16n8k16.row.col.f32.bf16.bf16.f32 "
        "{%0,%1,%2,%3}, {%4,%5,%6,%7}, {%8,%9}, {%0,%1,%2,%3};"
        : "+f"(d[0]), "+f"(d[1]), "+f"(d[2]), "+f"(d[3])
        : "r"(a[0]), "r"(a[1]), "r"(a[2]), "r"(a[3]), "r"(b[0]), "r"(b[1]));
}

__device__ __forceinline__ void ldsm4(unsigned r[4], unsigned addr) {
    asm volatile(
        "ldmatrix.sync.aligned.m8n8.x4.shared.b16 {%0,%1,%2,%3}, [%4];"
        : "=r"(r[0]), "=r"(r[1]), "=r"(r[2]), "=r"(r[3]) : "r"(addr));
}

// K-split partial GEMM (R14 core, unchanged): P[z][m,n] = partial over this
// CTA's 1/gridDim.z share of K tiles. Producer: LDG fp32 -> register split ->
// STS bf16 hi/lo; double-buffered planes, ONE __syncthreads per tile.
// D = Ah*Wh + Ah*Wl + Al*Wh. BM=64, BK=32; 256 thr, warps 2m x 2n x 2k.
template<int BN>
__global__ __launch_bounds__(256)
void gemm_ks(const float* __restrict__ A1, int lda1,
             const float* __restrict__ W1, int K1,
             const float* __restrict__ A2, int lda2,
             const float* __restrict__ W2, int K2,
             float* __restrict__ P, int pstride)
{
    constexpr int PKB  = 40;                     // bf16 pitch (80B rows)
    constexpr int APB  = 64 * 80;                // A plane bytes
    constexpr int BPB  = BN * 80;                // B plane bytes
    constexpr int BUFB = 2 * APB + 2 * BPB;      // AHI|ALO|BHI|BLO
    constexpr int WNJ  = BN / 16;
    constexpr int WIW  = BN / 32;

    __shared__ __align__(16) char sm[2 * BUFB];  // 40KB (BN=64) static

    const int tid  = threadIdx.x;
    const int lane = tid & 31;
    const int wid  = tid >> 5;
    const int wk   = wid & 1;
    const int wm   = (wid >> 1) & 1;
    const int wn   = wid >> 2;
    const int bm   = blockIdx.y * 64;
    const int bn   = blockIdx.x * BN;
    const int lr   = lane >> 2;
    const int lc   = lane & 3;
    const int k0   = wk * 16;

    const int t1   = K1 >> 5;
    const int tTot = t1 + (K2 >> 5);
    const int shr  = tTot / (int)gridDim.z;      // 32 for cell(z=3) and fc(z=2)
    const int tBeg = blockIdx.z * shr;
    const int tEnd = tBeg + shr;

    const int ldr  = tid >> 3;                   // 0..31
    const int ldc4 = (tid & 7) * 4;              // fp32 chunk in BK=32

    // ldmatrix byte offsets within a plane (R7/R13-proven formulas)
    const int offA = ((wm * 32 + ((lane >> 3) & 1) * 8 + (lane & 7)) * PKB
                      + k0 + (lane >> 4) * 8) * 2;
    const int offB = ((wn * (BN / 2) + (lane >> 4) * 8 + (lane & 7)) * PKB
                      + k0 + ((lane >> 3) & 1) * 8) * 2;
    const unsigned smBase = smem_u32(sm);

    float4 av[2];
    float4 wv[WIW];

#define LDTILE(TT)                                                           \
    do {                                                                     \
        const float *A_, *W_; int lda_, K_, kt_;                             \
        if ((TT) < t1) { A_ = A1; W_ = W1; lda_ = lda1; K_ = K1; kt_ = (TT) << 5; } \
        else           { A_ = A2; W_ = W2; lda_ = lda2; K_ = K2; kt_ = ((TT) - t1) << 5; } \
        _Pragma("unroll")                                                    \
        for (int p = 0; p < 2; p++)                                          \
            av[p] = *(const float4*)(A_ + (size_t)(bm + ldr + p * 32) * lda_ + kt_ + ldc4); \
        _Pragma("unroll")                                                    \
        for (int p = 0; p < WIW; p++)                                        \
            wv[p] = *(const float4*)(W_ + (size_t)(bn + ldr + p * 32) * K_ + kt_ + ldc4); \
    } while (0)

#define STTILE(BUF)                                                          \
    do {                                                                     \
        char* AHI_ = sm + (BUF) * BUFB;                                      \
        char* ALO_ = AHI_ + APB;                                             \
        char* BHI_ = ALO_ + APB;                                             \
        char* BLO_ = BHI_ + BPB;                                             \
        _Pragma("unroll")                                                    \
        for (int p = 0; p < 2; p++) {                                        \
            int r = ldr + p * 32;                                            \
            uint2 H, L; split4(av[p], H, L);                                 \
            *(uint2*)(AHI_ + r * 80 + ldc4 * 2) = H;                         \
            *(uint2*)(ALO_ + r * 80 + ldc4 * 2) = L;                         \
        }                                                                    \
        _Pragma("unroll")                                                    \
        for (int p = 0; p < WIW; p++) {                                      \
            int r = ldr + p * 32;                                            \
            uint2 H, L; split4(wv[p], H, L);                                 \
            *(uint2*)(BHI_ + r * 80 + ldc4 * 2) = H;                         \
            *(uint2*)(BLO_ + r * 80 + ldc4 * 2) = L;                         \
        }                                                                    \
    } while (0)

    float D[2][WNJ][4];
    #pragma unroll
    for (int i = 0; i < 2; i++)
        #pragma unroll
        for (int j = 0; j < WNJ; j++)
            #pragma unroll
            for (int q = 0; q < 4; q++) D[i][j][q] = 0.0f;

    LDTILE(tBeg);

    for (int t = tBeg; t < tEnd; t++) {
        const int buf = t & 1;
        STTILE(buf);
        __syncthreads();                         // the only sync per tile
        if (t + 1 < tEnd) LDTILE(t + 1);         // flight covers MMA phase

        const unsigned aHi = smBase + buf * BUFB + offA;
        const unsigned aLo = aHi + APB;
        const unsigned bHi = aLo + APB - offA + offB;
        const unsigned bLo = bHi + BPB;

        unsigned Ah[2][4], Al[2][4];
        #pragma unroll
        for (int mi = 0; mi < 2; mi++) {
            ldsm4(Ah[mi], aHi + mi * (16 * 80));
            ldsm4(Al[mi], aLo + mi * (16 * 80));
        }
        unsigned Bh[WNJ][2], Bl[WNJ][2];
        #pragma unroll
        for (int p = 0; p < WNJ / 2; p++) {
            unsigned t4[4];
            ldsm4(t4, bHi + p * (16 * 80));
            Bh[2*p][0] = t4[0]; Bh[2*p][1] = t4[1];
            Bh[2*p+1][0] = t4[2]; Bh[2*p+1][1] = t4[3];
            ldsm4(t4, bLo + p * (16 * 80));
            Bl[2*p][0] = t4[0]; Bl[2*p][1] = t4[1];
            Bl[2*p+1][0] = t4[2]; Bl[2*p+1][1] = t4[3];
        }
        #pragma unroll
        for (int mi = 0; mi < 2; mi++)
            #pragma unroll
            for (int nj = 0; nj < WNJ; nj++) {
                mma16816(D[mi][nj], Ah[mi], Bh[nj]);
                mma16816(D[mi][nj], Ah[mi], Bl[nj]);
                mma16816(D[mi][nj], Al[mi], Bh[nj]);
            }
    }
#undef LDTILE
#undef STTILE

    __syncthreads();                             // all ldsm done; smem reusable

    // ---- combine the two warp-level k16-partials through smem ----
    float* sRed = (float*)sm;
    const int rebase = (wm * 2 + wn) * 32 + lane;
    if (wk == 1) {
        #pragma unroll
        for (int mi = 0; mi < 2; mi++)
            #pragma unroll
            for (int nj = 0; nj < WNJ; nj++)
                #pragma unroll
                for (int q = 0; q < 4; q++)
                    sRed[((mi * WNJ + nj) * 4 + q) * 128 + rebase] = D[mi][nj][q];
    }
    __syncthreads();
    if (wk == 0) {
        float* Pk = P + (size_t)blockIdx.z * pstride;
        const int N = gridDim.x * BN;
        #pragma unroll
        for (int mi = 0; mi < 2; mi++)
            #pragma unroll
            for (int nj = 0; nj < WNJ; nj++) {
                #pragma unroll
                for (int q = 0; q < 4; q++)
                    D[mi][nj][q] += sRed[((mi * WNJ + nj) * 4 + q) * 128 + rebase];
                int r = bm + wm * 32 + mi * 16 + lr;
                int c = bn + wn * (BN / 2) + nj * 8 + lc * 2;
                *(float2*)(Pk + (size_t)r * N + c) =
                    make_float2(D[mi][nj][0], D[mi][nj][1]);
                *(float2*)(Pk + (size_t)(r + 8) * N + c) =
                    make_float2(D[mi][nj][2], D[mi][nj][3]);
            }
    }
}

// out[r, c] = act(sum_z p[z] + bias[c]); float4-vectorized, NP partials.
template<int NP, bool RELU>
__global__ void reduce_kernel(const float4* __restrict__ p,
                              int pstride4,
                              const float* __restrict__ bias,
                              float* __restrict__ out,
                              int N4, int ldc, int total4)
{
    int i = blockIdx.x * blockDim.x + threadIdx.x;
    if (i >= total4) return;
    int row = i / N4, c4 = i % N4;
    float4 v = p[i];
    #pragma unroll
    for (int z = 1; z < NP; z++) {
        float4 a = p[i + (size_t)z * pstride4];
        v.x += a.x; v.y += a.y; v.z += a.z; v.w += a.w;
    }
    float4 bb = *(const float4*)&bias[c4 * 4];
    v.x += bb.x; v.y += bb.y; v.z += bb.z; v.w += bb.w;
    if (RELU) {
        v.x = fmaxf(v.x, 0.0f); v.y = fmaxf(v.y, 0.0f);
        v.z = fmaxf(v.z, 0.0f); v.w = fmaxf(v.w, 0.0f);
    }
    *(float4*)(out + (size_t)row * ldc + c4 * 4) = v;
}

extern "C" void kernel_launch(void* const* d_in, const int* in_sizes, int n_in,
                              void* d_out, int out_size)
{
    const float* inputs = (const float*)d_in[0];   // [256,128,1024]
    const float* W_ih   = (const float*)d_in[1];   // [2048,1024]
    const float* b_ih   = (const float*)d_in[2];
    const float* W_hh   = (const float*)d_in[3];   // [2048,2048]
    const float* b_hh   = (const float*)d_in[4];
    const float* W_fc   = (const float*)d_in[5];   // [1024,2048]
    const float* b_fc   = (const float*)d_in[6];
    float* out = (float*)d_out;                    // [256,129,1024]

    float* h_base = nullptr; float* part = nullptr; float* fcpart = nullptr;
    float* bias_cell = nullptr;
    cudaGetSymbolAddress((void**)&h_base, g_h);
    cudaGetSymbolAddress((void**)&part, g_part);
    cudaGetSymbolAddress((void**)&fcpart, g_fcpart);
    cudaGetSymbolAddress((void**)&bias_cell, g_bias_cell);
    float* h[2] = { h_base, h_base + (size_t)BATCH * HID };
    const int PSTRIDE  = BATCH * HID;
    const int FCSTRIDE = BATCH * FEAT;

    init_kernel<<<(BATCH * HID + 255) / 256, 256>>>(b_ih, b_hh);

    dim3 cellGrid(HID / 64, BATCH / 64, 3);   // 32 x 4 x 3 = 384 CTAs, 32 tiles each
    dim3 fcGrid(FEAT / 32, BATCH / 64, 2);    // 32 x 4 x 2 = 256 CTAs, 32 tiles each

    const int cellT4 = BATCH * HID / 4;
    const int fcT4   = BATCH * FEAT / 4;

    int cur = 0;
    for (int t = 0; t < NWARM; t++) {
        gemm_ks<64><<<cellGrid, 256>>>(
            inputs + (size_t)t * FEAT, NWARM * FEAT, W_ih, FEAT,
            h[cur], HID, W_hh, HID,
            part, PSTRIDE);
        reduce_kernel<3, true><<<(cellT4 + 255) / 256, 256>>>(
            (const float4*)part, PSTRIDE / 4,
            bias_cell, h[cur ^ 1], HID / 4, HID, cellT4);
        cur ^= 1;
    }
    gemm_ks<32><<<fcGrid, 256>>>(
        h[cur], HID, W_fc, HID,
        nullptr, 0, nullptr, 0,
        fcpart, FCSTRIDE);
    reduce_kernel<2, false><<<(fcT4 + 255) / 256, 256>>>(
        (const float4*)fcpart, FCSTRIDE / 4,
        b_fc, out, FEAT / 4, LDOUT, fcT4);
    for (int s = 1; s <= TSTEPS; s++) {
        gemm_ks<64><<<cellGrid, 256>>>(
            out + (size_t)(s - 1) * FEAT, LDOUT, W_ih, FEAT,
            h[cur], HID, W_hh, HID,
            part, PSTRIDE);
        reduce_kernel<3, true><<<(cellT4 + 255) / 256, 256>>>(
            (const float4*)part, PSTRIDE / 4,
            bias_cell, h[cur ^ 1], HID / 4, HID, cellT4);
        cur ^= 1;
        gemm_ks<32><<<fcGrid, 256>>>(
            h[cur], HID, W_fc, HID,
            nullptr, 0, nullptr, 0,
            fcpart, FCSTRIDE);
        reduce_kernel<2, false><<<(fcT4 + 255) / 256, 256>>>(
            (const float4*)fcpart, FCSTRIDE / 4,
            b_fc, out + (size_t)s * FEAT, FEAT / 4, LDOUT, fcT4);
    }
}